// round 1
// baseline (speedup 1.0000x reference)
#include <cuda_runtime.h>
#include <stdint.h>

#define BB 8
#define NN 50000
#define CC 80
#define KK 500        // per-class candidate cap
#define MAXD 300      // max detections
#define FLATN (CC*KK) // 40000

// ---------------- device scratch (static, allocation-free) ----------------
__device__ unsigned int g_keys[(size_t)BB * CC * NN];   // 128 MB: [B][C][N] score keys
__device__ unsigned int g_cand_key[BB * CC * KK];       // per-class top-500 score keys
__device__ int          g_cand_idx[BB * CC * KK];       // per-class top-500 box indices
__device__ unsigned int g_kept_key[BB * CC * KK];       // post-NMS kept score keys (else 0)

// ---------------- K1: transpose + keyify ----------------
// classification [B,N,C] -> g_keys [B,C,N]; key = bits(s) if s>0.05 else 0.
__global__ void k_transpose(const float* __restrict__ cls) {
    __shared__ float tile[32][33];
    int b = blockIdx.z;
    int n0 = blockIdx.x * 32, c0 = blockIdx.y * 32;
    int tx = threadIdx.x, ty = threadIdx.y; // 32x8
    const float* src = cls + (size_t)b * NN * CC;
    #pragma unroll
    for (int i = 0; i < 32; i += 8) {
        int n = n0 + ty + i, c = c0 + tx;
        tile[ty + i][tx] = (n < NN && c < CC) ? src[(size_t)n * CC + c] : 0.f;
    }
    __syncthreads();
    unsigned int* dst = g_keys + (size_t)b * CC * NN;
    #pragma unroll
    for (int i = 0; i < 32; i += 8) {
        int c = c0 + ty + i, n = n0 + tx;
        if (c < CC && n < NN) {
            float s = tile[tx][ty + i];
            dst[(size_t)c * NN + n] = (s > 0.05f) ? __float_as_uint(s) : 0u;
        }
    }
}

// ---------------- K2: exact top-500 per (b,c) ----------------
// 4-pass MSB radix select for the 500th key, then gather + bitonic sort
// on (key desc, idx asc) to match jax.lax.top_k semantics exactly.
__global__ void k_select() {
    const int T = 256;
    int bc = blockIdx.x;
    const unsigned int* col = g_keys + (size_t)bc * NN;
    __shared__ unsigned int hist[256];
    __shared__ unsigned int s_prefix, s_maskhi, s_rem;
    __shared__ unsigned long long ent[1024];
    __shared__ int s_g, s_e;
    int tid = threadIdx.x;

    if (tid == 0) { s_prefix = 0u; s_maskhi = 0u; s_rem = KK; }
    __syncthreads();

    for (int p = 0; p < 4; p++) {
        int shift = 24 - 8 * p;
        hist[tid] = 0u;
        __syncthreads();
        unsigned pf = s_prefix, mh = s_maskhi;
        for (int i = tid; i < NN; i += T) {
            unsigned k = col[i];
            if ((k & mh) == pf) atomicAdd(&hist[(k >> shift) & 255u], 1u);
        }
        __syncthreads();
        if (tid == 0) {
            unsigned rem = s_rem, cum = 0; int chosen = 0;
            for (int bn = 255; bn >= 0; bn--) {
                unsigned c2 = cum + hist[bn];
                if (c2 >= rem) { chosen = bn; break; }
                cum = c2;
            }
            s_rem = rem - cum;                 // still needed from chosen bin (>=1)
            s_prefix = pf | ((unsigned)chosen << shift);
            s_maskhi = mh | (255u << shift);
        }
        __syncthreads();
    }
    unsigned Tkey = s_prefix;
    if (tid == 0) { s_g = 0; s_e = 0; }
    for (int i = tid; i < 1024; i += T) ent[i] = 0ull;
    __syncthreads();

    // gather: strictly-greater (count <= 499 by select invariant) at [0..],
    // ties (==Tkey) at [512..], capped.
    for (int i = tid; i < NN; i += T) {
        unsigned k = col[i];
        if (k > Tkey) {
            int p = atomicAdd(&s_g, 1);
            ent[p] = ((unsigned long long)k << 32) | (unsigned)(~(unsigned)i);
        } else if (k == Tkey && s_e < 512) {
            int p = atomicAdd(&s_e, 1);
            if (p < 512)
                ent[512 + p] = ((unsigned long long)k << 32) | (unsigned)(~(unsigned)i);
        }
    }
    __syncthreads();

    // bitonic sort, DESCENDING on packed (key, ~idx) -> key desc, idx asc
    for (int k2 = 2; k2 <= 1024; k2 <<= 1) {
        for (int j = k2 >> 1; j > 0; j >>= 1) {
            for (int i = tid; i < 1024; i += T) {
                int ixj = i ^ j;
                if (ixj > i) {
                    unsigned long long a = ent[i], b2 = ent[ixj];
                    bool up = ((i & k2) == 0);
                    if (up ? (a < b2) : (a > b2)) { ent[i] = b2; ent[ixj] = a; }
                }
            }
            __syncthreads();
        }
    }
    for (int s = tid; s < KK; s += T) {
        unsigned long long e = ent[s];
        g_cand_key[bc * KK + s] = (unsigned)(e >> 32);
        g_cand_idx[bc * KK + s] = (int)(~(unsigned)e);
    }
}

// ---------------- K3: greedy NMS per (b,c) ----------------
__global__ void k_nms(const float* __restrict__ boxes) {
    const int T = 256;
    int bc = blockIdx.x;
    int b = bc / CC;
    __shared__ float4 sbox[KK];
    __shared__ float  sarea[KK];
    __shared__ unsigned skey[KK];
    __shared__ unsigned mask[KK][16];  // suppression bitmask rows (j>i)
    __shared__ unsigned keepw[16];
    __shared__ int kbase[16];
    int tid = threadIdx.x;
    const float* bx = boxes + (size_t)b * NN * 4;

    for (int k = tid; k < KK; k += T) {
        unsigned key = g_cand_key[bc * KK + k];
        skey[k] = key;
        float4 bb = make_float4(0.f, 0.f, 0.f, 0.f);
        if (key) {
            int idx = g_cand_idx[bc * KK + k];
            bb = *reinterpret_cast<const float4*>(bx + (size_t)idx * 4);
        }
        sbox[k] = bb;
        sarea[k] = fmaxf(bb.z - bb.x, 0.f) * fmaxf(bb.w - bb.y, 0.f);
    }
    __syncthreads();

    // pairwise IoU mask, row r owns bits j>r
    for (int r = tid; r < KK; r += T) {
        float4 bi = sbox[r]; float ai = sarea[r];
        unsigned m[16];
        #pragma unroll
        for (int w = 0; w < 16; w++) m[w] = 0u;
        for (int j = r + 1; j < KK; j++) {
            float4 bj = sbox[j];
            float yy1 = fmaxf(bi.x, bj.x), xx1 = fmaxf(bi.y, bj.y);
            float yy2 = fminf(bi.z, bj.z), xx2 = fminf(bi.w, bj.w);
            float inter = fmaxf(yy2 - yy1, 0.f) * fmaxf(xx2 - xx1, 0.f);
            float iou = inter / (ai + sarea[j] - inter + 1e-9f);
            if (iou > 0.5f) m[j >> 5] |= 1u << (j & 31);
        }
        #pragma unroll
        for (int w = 0; w < 16; w++) mask[r][w] = m[w];
    }
    __syncthreads();

    // warp-cooperative greedy sweep: lanes 0..15 own suppression words
    if (tid < 32) {
        int lane = tid;
        unsigned sup = 0u, kw = 0u;
        for (int i = 0; i < KK; i++) {
            int w = i >> 5, bb2 = i & 31;
            unsigned supw = __shfl_sync(0xffffffffu, sup, w);
            bool kept = (skey[i] != 0u) && !((supw >> bb2) & 1u);
            if (kept) {
                if (lane < 16) sup |= mask[i][lane];
                if (lane == w) kw |= 1u << bb2;
            }
        }
        if (lane < 16) keepw[lane] = kw;
        int cnt = (lane < 16) ? __popc(kw) : 0;
        int v = cnt;
        for (int off = 1; off < 32; off <<= 1) {
            int t2 = __shfl_up_sync(0xffffffffu, v, off);
            if (lane >= off) v += t2;
        }
        if (lane < 16) kbase[lane] = v - cnt; // exclusive prefix
    }
    __syncthreads();

    // apply keep + cumsum<=300 cap; write kept-score keys
    for (int k = tid; k < KK; k += T) {
        int w = k >> 5, bb2 = k & 31;
        unsigned kwv = keepw[w];
        bool kept = (kwv >> bb2) & 1u;
        int rank = kbase[w] + __popc(kwv & ((1u << bb2) - 1u));
        kept = kept && (rank < MAXD);
        g_kept_key[bc * KK + k] = kept ? skey[k] : 0u;
    }
}

// ---------------- K4: global top-300 per image + output ----------------
__global__ void k_final(const float* __restrict__ boxes, float* __restrict__ out) {
    const int T = 256;
    int b = blockIdx.x;
    const unsigned int* col = g_kept_key + b * FLATN;
    __shared__ unsigned int hist[256];
    __shared__ unsigned int s_prefix, s_maskhi, s_rem;
    __shared__ unsigned long long ent[1024];
    __shared__ int s_g, s_e;
    int tid = threadIdx.x;

    if (tid == 0) { s_prefix = 0u; s_maskhi = 0u; s_rem = MAXD; }
    __syncthreads();

    for (int p = 0; p < 4; p++) {
        int shift = 24 - 8 * p;
        hist[tid] = 0u;
        __syncthreads();
        unsigned pf = s_prefix, mh = s_maskhi;
        for (int i = tid; i < FLATN; i += T) {
            unsigned k = col[i];
            if ((k & mh) == pf) atomicAdd(&hist[(k >> shift) & 255u], 1u);
        }
        __syncthreads();
        if (tid == 0) {
            unsigned rem = s_rem, cum = 0; int chosen = 0;
            for (int bn = 255; bn >= 0; bn--) {
                unsigned c2 = cum + hist[bn];
                if (c2 >= rem) { chosen = bn; break; }
                cum = c2;
            }
            s_rem = rem - cum;
            s_prefix = pf | ((unsigned)chosen << shift);
            s_maskhi = mh | (255u << shift);
        }
        __syncthreads();
    }
    unsigned Tkey = s_prefix;
    if (tid == 0) { s_g = 0; s_e = 0; }
    for (int i = tid; i < 1024; i += T) ent[i] = 0ull;
    __syncthreads();

    for (int i = tid; i < FLATN; i += T) {
        unsigned k = col[i];
        if (k > Tkey) {
            int p = atomicAdd(&s_g, 1);
            ent[p] = ((unsigned long long)k << 32) | (unsigned)(~(unsigned)i);
        } else if (k == Tkey && s_e < 512) {
            int p = atomicAdd(&s_e, 1);
            if (p < 512)
                ent[512 + p] = ((unsigned long long)k << 32) | (unsigned)(~(unsigned)i);
        }
    }
    __syncthreads();

    for (int k2 = 2; k2 <= 1024; k2 <<= 1) {
        for (int j = k2 >> 1; j > 0; j >>= 1) {
            for (int i = tid; i < 1024; i += T) {
                int ixj = i ^ j;
                if (ixj > i) {
                    unsigned long long a = ent[i], b2 = ent[ixj];
                    bool up = ((i & k2) == 0);
                    if (up ? (a < b2) : (a > b2)) { ent[i] = b2; ent[ixj] = a; }
                }
            }
            __syncthreads();
        }
    }

    // output: boxes [B,300,4] || scores [B,300] || labels [B,300] (as float)
    float* oB = out;
    float* oS = out + (size_t)BB * MAXD * 4;
    float* oL = out + (size_t)BB * MAXD * 4 + (size_t)BB * MAXD;
    const float* bx = boxes + (size_t)b * NN * 4;
    for (int s = tid; s < MAXD; s += T) {
        unsigned long long e = ent[s];
        unsigned key = (unsigned)(e >> 32);
        float4 bb; float sc, lb;
        if (key) {
            unsigned fidx = ~(unsigned)e;           // flat index into [C*K]
            int c = (int)(fidx / KK);
            int k = (int)(fidx % KK);
            int idx = g_cand_idx[(b * CC + c) * KK + k];
            bb = *reinterpret_cast<const float4*>(bx + (size_t)idx * 4);
            sc = __uint_as_float(key);
            lb = (float)c;
        } else {
            bb = make_float4(-1.f, -1.f, -1.f, -1.f);
            sc = -1.f; lb = -1.f;
        }
        size_t row = (size_t)b * MAXD + s;
        oB[row * 4 + 0] = bb.x; oB[row * 4 + 1] = bb.y;
        oB[row * 4 + 2] = bb.z; oB[row * 4 + 3] = bb.w;
        oS[row] = sc;
        oL[row] = lb;
    }
}

// ---------------- launch ----------------
extern "C" void kernel_launch(void* const* d_in, const int* in_sizes, int n_in,
                              void* d_out, int out_size) {
    const float* boxes = (const float*)d_in[0];          // [8,50000,4]
    const float* cls   = (const float*)d_in[1];          // [8,50000,80]
    (void)in_sizes; (void)n_in; (void)out_size;

    dim3 bt(32, 8);
    dim3 bg((NN + 31) / 32, (CC + 31) / 32, BB);
    k_transpose<<<bg, bt>>>(cls);
    k_select<<<BB * CC, 256>>>();
    k_nms<<<BB * CC, 256>>>(boxes);
    k_final<<<BB, 256>>>(boxes, (float*)d_out);
}